// round 1
// baseline (speedup 1.0000x reference)
#include <cuda_runtime.h>
#include <cuda_bf16.h>

// PolyLoss: N=4096 rows, V=128 shifts/positions, last dim = 2 (float2).
// per_shift[n,s] = (1/V) * sum_v |pred[n,(s+v)%V] - gt[n,v]|_1
// loss = mean_n min_s per_shift[n,s]
//
// Kernel 1: one CTA per row, one thread per shift. Row data staged in smem.
// Kernel 2: deterministic tree reduction of the 4096 per-row minima.

#define NROWS 4096
#define V 128

__device__ float g_rowmin[NROWS];

__global__ void __launch_bounds__(V, 8) polyloss_row_kernel(
    const float* __restrict__ pred, const float* __restrict__ gt)
{
    __shared__ float2 sp[V];
    __shared__ float2 sg[V];
    __shared__ float warp_min[V / 32];

    const int row = blockIdx.x;
    const int t = threadIdx.x;

    // Stage this row: 128 float2 for pred, 128 float2 for gt (coalesced 8B loads)
    const float2* p = reinterpret_cast<const float2*>(pred) + row * V;
    const float2* g = reinterpret_cast<const float2*>(gt) + row * V;
    sp[t] = p[t];
    sg[t] = g[t];
    __syncthreads();

    // Thread t computes the sum for shift s = t.
    // sp[(t+v)&127] is a per-v rotation: all 32 lanes hit distinct indices
    // -> conflict-free. sg[v] is a broadcast -> conflict-free.
    float a0 = 0.f, a1 = 0.f, a2 = 0.f, a3 = 0.f;
    #pragma unroll
    for (int v = 0; v < V; v += 4) {
        float2 p0 = sp[(t + v + 0) & (V - 1)];
        float2 p1 = sp[(t + v + 1) & (V - 1)];
        float2 p2 = sp[(t + v + 2) & (V - 1)];
        float2 p3 = sp[(t + v + 3) & (V - 1)];
        float2 g0 = sg[v + 0];
        float2 g1 = sg[v + 1];
        float2 g2 = sg[v + 2];
        float2 g3 = sg[v + 3];
        a0 += fabsf(p0.x - g0.x) + fabsf(p0.y - g0.y);
        a1 += fabsf(p1.x - g1.x) + fabsf(p1.y - g1.y);
        a2 += fabsf(p2.x - g2.x) + fabsf(p2.y - g2.y);
        a3 += fabsf(p3.x - g3.x) + fabsf(p3.y - g3.y);
    }
    float acc = (a0 + a1) + (a2 + a3);

    // Min over shifts: warp shuffle reduction, then across the 4 warps.
    #pragma unroll
    for (int off = 16; off > 0; off >>= 1)
        acc = fminf(acc, __shfl_xor_sync(0xffffffffu, acc, off));
    if ((t & 31) == 0) warp_min[t >> 5] = acc;
    __syncthreads();
    if (t == 0) {
        float m = fminf(fminf(warp_min[0], warp_min[1]),
                        fminf(warp_min[2], warp_min[3]));
        g_rowmin[row] = m;
    }
}

__global__ void polyloss_reduce_kernel(float* __restrict__ out)
{
    __shared__ float s[256];
    const int t = threadIdx.x;
    float acc = 0.f;
    #pragma unroll
    for (int i = t; i < NROWS; i += 256)
        acc += g_rowmin[i];
    s[t] = acc;
    __syncthreads();
    #pragma unroll
    for (int off = 128; off > 0; off >>= 1) {
        if (t < off) s[t] += s[t + off];
        __syncthreads();
    }
    if (t == 0)
        out[0] = s[0] * (1.0f / ((float)NROWS * (float)V));
}

extern "C" void kernel_launch(void* const* d_in, const int* in_sizes, int n_in,
                              void* d_out, int out_size)
{
    const float* pred = (const float*)d_in[0];
    const float* gt   = (const float*)d_in[1];
    float* out = (float*)d_out;

    polyloss_row_kernel<<<NROWS, V>>>(pred, gt);
    polyloss_reduce_kernel<<<1, 256>>>(out);
}

// round 2
// speedup vs baseline: 1.6081x; 1.6081x over previous
#include <cuda_runtime.h>
#include <cstdint>

// PolyLoss: N=4096 rows, V=128 circular shifts, last dim = 2 (packed f32x2).
// per_shift[n,s] = sum_v |pred[n,(s+v)%V] - gt[n,v]|_1 ; loss = mean_n min_s / (N*V)
//
// One warp per row (thread t owns shifts 4t..4t+3, sliding register window over
// pred positions). Packed f32x2 math: 4 SASS instr per (shift,v) pair split
// 2 fma-pipe / 2 alu-pipe. Fused final reduction via last-CTA ticket.

#define NROWS 4096
#define V 128
#define RPC 4                 // rows per CTA (1 warp per row)
#define NCTA (NROWS / RPC)    // 1024
#define THREADS 128

__device__ float g_partial[NCTA];
__device__ int g_ctr;

__device__ __forceinline__ uint64_t fma2(uint64_t a, uint64_t b, uint64_t c) {
    uint64_t d;
    asm("fma.rn.f32x2 %0, %1, %2, %3;" : "=l"(d) : "l"(a), "l"(b), "l"(c));
    return d;
}

// acc += | p - g |  (componentwise, packed): FFMA2 + 2xLOP3 + FFMA2
#define ACC(p2, g2, acc) do {                      \
    uint64_t _d = fma2((g2), NEG1, (p2));          \
    _d &= 0x7fffffff7fffffffULL;                   \
    (acc) = fma2(_d, ONE1, (acc));                 \
} while (0)

__global__ void __launch_bounds__(THREADS) polyloss_kernel(
    const float* __restrict__ pred, const float* __restrict__ gt,
    float* __restrict__ out)
{
    // sp: pred positions duplicated (132 ulonglong2 = 264 float2 positions).
    // Each ulonglong2 = two packed-f32x2 positions. sg: gt row (64 entries).
    __shared__ ulonglong2 sp[RPC][132];
    __shared__ ulonglong2 sg[RPC][64];
    __shared__ float s_rowmin[RPC];
    __shared__ int s_is_last;
    __shared__ float s_red[THREADS];

    const int tid  = threadIdx.x;
    const int w    = tid >> 5;          // warp = row within CTA
    const int lane = tid & 31;
    const int row  = blockIdx.x * RPC + w;

    const uint64_t NEG1 = 0xBF800000BF800000ULL;  // (-1.f, -1.f)
    const uint64_t ONE1 = 0x3F8000003F800000ULL;  // ( 1.f,  1.f)

    // ---- stage row: 64 ulonglong2 pred (duplicated 2x + 4 extra), 64 gt ----
    {
        const ulonglong2* prow = reinterpret_cast<const ulonglong2*>(pred) + row * 64;
        const ulonglong2* grow = reinterpret_cast<const ulonglong2*>(gt)   + row * 64;
        ulonglong2 r0 = prow[lane];
        ulonglong2 r1 = prow[lane + 32];
        sp[w][lane]      = r0;
        sp[w][lane + 32] = r1;
        sp[w][lane + 64] = r0;
        sp[w][lane + 96] = r1;
        if (lane < 4) sp[w][lane + 128] = r0;
        sg[w][lane]      = grow[lane];
        sg[w][lane + 32] = grow[lane + 32];
    }
    __syncwarp();

    // ---- main loop: thread t computes shifts 4t..4t+3 ----
    // Window Fa..Fd = positions k..k+7, k = 4*lane + v. Per iter: 4 v's,
    // 16 (shift,v) pairs, 2 LDS.128 pred prefetch + 2 LDS.128 gt.
    uint64_t a0 = 0, a1 = 0, a2 = 0, a3 = 0;
    const int base = 2 * lane;
    ulonglong2 Fa = sp[w][base + 0];
    ulonglong2 Fb = sp[w][base + 1];
    ulonglong2 Fc = sp[w][base + 2];
    ulonglong2 Fd = sp[w][base + 3];

    #pragma unroll 4
    for (int m = 0; m < 32; m++) {
        ulonglong2 G0 = sg[w][2 * m];       // gt[v], gt[v+1]
        ulonglong2 G1 = sg[w][2 * m + 1];   // gt[v+2], gt[v+3]
        // v+0: positions k..k+3
        ACC(Fa.x, G0.x, a0); ACC(Fa.y, G0.x, a1); ACC(Fb.x, G0.x, a2); ACC(Fb.y, G0.x, a3);
        // v+1: positions k+1..k+4
        ACC(Fa.y, G0.y, a0); ACC(Fb.x, G0.y, a1); ACC(Fb.y, G0.y, a2); ACC(Fc.x, G0.y, a3);
        // v+2: positions k+2..k+5
        ACC(Fb.x, G1.x, a0); ACC(Fb.y, G1.x, a1); ACC(Fc.x, G1.x, a2); ACC(Fc.y, G1.x, a3);
        // v+3: positions k+3..k+6
        ACC(Fb.y, G1.y, a0); ACC(Fc.x, G1.y, a1); ACC(Fc.y, G1.y, a2); ACC(Fd.x, G1.y, a3);
        // slide window by 4 positions (2 entries); last-iter loads are
        // in-bounds (<132) and unused.
        Fa = Fc; Fb = Fd;
        Fc = sp[w][base + 2 * m + 4];
        Fd = sp[w][base + 2 * m + 5];
    }

    // ---- per-shift totals, warp min ----
    float s0 = __uint_as_float((uint32_t)a0) + __uint_as_float((uint32_t)(a0 >> 32));
    float s1 = __uint_as_float((uint32_t)a1) + __uint_as_float((uint32_t)(a1 >> 32));
    float s2 = __uint_as_float((uint32_t)a2) + __uint_as_float((uint32_t)(a2 >> 32));
    float s3 = __uint_as_float((uint32_t)a3) + __uint_as_float((uint32_t)(a3 >> 32));
    float mn = fminf(fminf(s0, s1), fminf(s2, s3));
    #pragma unroll
    for (int off = 16; off > 0; off >>= 1)
        mn = fminf(mn, __shfl_xor_sync(0xffffffffu, mn, off));
    if (lane == 0) s_rowmin[w] = mn;
    __syncthreads();

    // ---- CTA partial + last-CTA ticket ----
    if (tid == 0) {
        float p = (s_rowmin[0] + s_rowmin[1]) + (s_rowmin[2] + s_rowmin[3]);
        g_partial[blockIdx.x] = p;
        __threadfence();
        int ticket = atomicAdd(&g_ctr, 1);
        s_is_last = (ticket == NCTA - 1);
    }
    __syncthreads();

    if (s_is_last) {
        __threadfence();
        float acc = 0.f;
        #pragma unroll
        for (int i = tid; i < NCTA; i += THREADS)
            acc += g_partial[i];
        s_red[tid] = acc;
        __syncthreads();
        #pragma unroll
        for (int off = THREADS / 2; off > 0; off >>= 1) {
            if (tid < off) s_red[tid] += s_red[tid + off];
            __syncthreads();
        }
        if (tid == 0) {
            out[0] = s_red[0] * (1.0f / ((float)NROWS * (float)V));
            g_ctr = 0;  // reset for next graph replay
        }
    }
}

extern "C" void kernel_launch(void* const* d_in, const int* in_sizes, int n_in,
                              void* d_out, int out_size)
{
    const float* pred = (const float*)d_in[0];
    const float* gt   = (const float*)d_in[1];
    polyloss_kernel<<<NCTA, THREADS>>>(pred, gt, (float*)d_out);
}